// round 4
// baseline (speedup 1.0000x reference)
#include <cuda_runtime.h>
#include <stdint.h>

// Output: [B, C, X, Y] fp32
#define BB 4
#define CC 256
#define XX 256
#define YY 256
#define TY 64            // y-cells per block

// Inverse index: dense cell (b,x,y) -> (feature row + 1), 0 = empty. 1 MB.
// Zero-initialized at module load; each gather block resets its exclusive
// 64-entry slice to 0, so every launch starts from all-zero state.
__device__ int d_inv[BB * XX * YY];

// ---------------------------------------------------------------------------
// Kernel 1: scatter (row index + 1) into d_inv. Bounds-guarded = mode="drop".
// ---------------------------------------------------------------------------
__global__ void build_inv_kernel(const int* __restrict__ coords, int n) {
    int i = blockIdx.x * blockDim.x + threadIdx.x;
    if (i >= n) return;
    int b = coords[3 * i + 0];
    int x = coords[3 * i + 1];
    int y = coords[3 * i + 2];
    if ((unsigned)b < BB && (unsigned)x < XX && (unsigned)y < YY) {
        d_inv[(b * XX + x) * YY + y] = i + 1;
    }
}

// ---------------------------------------------------------------------------
// Kernel 2: transpose-tile gather. One block = 64 consecutive y cells of one
// (b, x) row, all 256 channels. 64 KB dynamic smem tile, XOR-swizzled:
//   element (c, y) at tile[c*64 + (y ^ ((c>>2) & 31))]
//
// Load phase: thread (yb8 = tid>>6, f = tid&63): LDG.128 of feats row
//   inv[y]-1, channels 4f..4f+3; warp = 512 B contiguous read. 4 rows
//   prefetched into registers before any STS -> MLP>=4/thread.
//   STS banks: (y ^ (f&31)) & 31, y fixed per warp, f&31 spans 0..31 ->
//   conflict-free.
// Store phase: warp w owns channels 16w..16w+15; per channel, lane l reads
//   (c, l) and (c, l+32) (banks l ^ const: conflict-free) and writes
//   out[...y=yb+l, yb+l+32] -> 2 full 128 B lines = 256 B contiguous per
//   channel per block.
//
// Every output element is written exactly once (zeros for empty cells).
// ---------------------------------------------------------------------------
__global__ void __launch_bounds__(512, 2)
gather_kernel(const float* __restrict__ feats, float* __restrict__ out) {
    __shared__ int s_inv[TY];
    extern __shared__ float tile[];      // CC * TY floats = 64 KB

    const int L  = blockIdx.x * TY;      // base linear cell index
    const int b  = L >> 16;              // / (XX*YY)
    const int x  = (L >> 8) & 255;       // / YY % XX
    const int yb = L & 255;              // % YY (multiple of 64)

    const int tid = threadIdx.x;

    // Stage inverse indices; reset exclusive slice to 0 for the next launch.
    if (tid < TY) {
        int v = d_inv[L + tid];
        s_inv[tid] = v;
        d_inv[L + tid] = 0;
    }
    __syncthreads();

    // ---- load phase: 8 y-rows per pass, 8 passes, prefetch depth 4 ----
    const int f   = tid & 63;            // float4 index within 256-ch row
    const int yb8 = tid >> 6;            // 0..7: row within pass
    const int sw  = f & 31;              // swizzle key

    #pragma unroll
    for (int g = 0; g < 2; g++) {
        float4 v[4];
        int    yv[4];
        #pragma unroll
        for (int q = 0; q < 4; q++) {
            const int y = (g * 4 + q) * 8 + yb8;
            yv[q] = y;
            const int r = s_inv[y];
            v[q] = make_float4(0.f, 0.f, 0.f, 0.f);
            if (r) {
                v[q] = *reinterpret_cast<const float4*>(
                           feats + (size_t)(r - 1) * CC + (f << 2));
            }
        }
        #pragma unroll
        for (int q = 0; q < 4; q++) {
            const int col = yv[q] ^ sw;
            tile[((f << 2) + 0) * TY + col] = v[q].x;
            tile[((f << 2) + 1) * TY + col] = v[q].y;
            tile[((f << 2) + 2) * TY + col] = v[q].z;
            tile[((f << 2) + 3) * TY + col] = v[q].w;
        }
    }
    __syncthreads();

    // ---- store phase: 256 B contiguous per channel ----
    const int warp = tid >> 5;           // 0..15 -> channels 16w..16w+15
    const int lane = tid & 31;
    float* op = out + ((size_t)b * CC) * (XX * YY) + (size_t)x * YY + yb;
    #pragma unroll
    for (int ci = 0; ci < 16; ci++) {
        const int c   = (warp << 4) + ci;
        const int swc = (c >> 2) & 31;
        const int base = c * TY;
        const float a0 = tile[base + (lane ^ swc)];
        const float a1 = tile[base + ((lane + 32) ^ swc)];
        float* p = op + (size_t)c * (XX * YY);
        p[lane]      = a0;
        p[lane + 32] = a1;
    }
}

// ---------------------------------------------------------------------------
// Launcher
// ---------------------------------------------------------------------------
extern "C" void kernel_launch(void* const* d_in, const int* in_sizes, int n_in,
                              void* d_out, int out_size) {
    const float* feats  = (const float*)d_in[0];
    const int*   coords = (const int*)d_in[1];
    float*       out    = (float*)d_out;

    const int n = in_sizes[1] / 3;  // number of sparse points

    const int smem = CC * TY * sizeof(float);   // 64 KB dynamic tile
    cudaFuncSetAttribute(gather_kernel,
                         cudaFuncAttributeMaxDynamicSharedMemorySize, smem);

    build_inv_kernel<<<(n + 255) / 256, 256>>>(coords, n);
    gather_kernel<<<(BB * XX * YY) / TY, 512, smem>>>(feats, out);
}

// round 5
// speedup vs baseline: 1.0354x; 1.0354x over previous
#include <cuda_runtime.h>
#include <stdint.h>

// Output: [B, C, X, Y] fp32
#define BB 4
#define CC 256
#define XX 256
#define YY 256
#define TY 32            // y-cells per block
#define XY (XX * YY)

// Inverse index: dense cell (b,x,y) -> (feature row + 1), 0 = empty. 1 MB.
// Zero-initialized at module load; each gather block resets its exclusive
// TY-entry slice to 0, so every launch starts from all-zero state.
__device__ int d_inv[BB * XX * YY];

// ---------------------------------------------------------------------------
// Kernel 1: scatter (row index + 1) into d_inv. Bounds-guarded = mode="drop".
// ---------------------------------------------------------------------------
__global__ void build_inv_kernel(const int* __restrict__ coords, int n) {
    int i = blockIdx.x * blockDim.x + threadIdx.x;
    if (i >= n) return;
    int b = coords[3 * i + 0];
    int x = coords[3 * i + 1];
    int y = coords[3 * i + 2];
    if ((unsigned)b < BB && (unsigned)x < XX && (unsigned)y < YY) {
        d_inv[(b * XX + x) * YY + y] = i + 1;
    }
}

// ---------------------------------------------------------------------------
// Kernel 2: cp.async transpose-tile gather.
// One block = 32 consecutive y cells of one (b, x) row, all 256 channels.
// Tile: float4 tile4[64][TY]; logical (f, y) = channels 4f..4f+3 of cell y,
// stored at column (y ^ (f & 31)).
//
// Load phase: thread (jb = tid>>6, f = tid&63) issues 8 independent
//   cp.async.cg 16 B copies (one per y-wave), src-size = 0 zero-fills empty
//   cells. No registers consumed -> full-depth MLP; 32 KB/block in flight.
//   Async-store banks: lanes' 16 B chunks tile all 32 banks 4-deep ->
//   4 phases / 512 B (optimal).
// Store phase: warp w, iter i: f = 8w+i; lane reads tile4[f][lane ^ (f&31)]
//   (LDS.128, 4 phases / 512 B) and writes 4 streaming STG.32, lanes
//   contiguous in y -> four full 128 B output lines per warp-iter.
//
// Every output element is written exactly once (zeros for empty cells), so
// the poisoned output is fully initialized here.
// ---------------------------------------------------------------------------
__global__ void __launch_bounds__(256)
gather_kernel(const float* __restrict__ feats, float* __restrict__ out) {
    __shared__ int    s_inv[TY];
    __shared__ float4 tile4[64 * TY];    // 32 KB

    const int L  = blockIdx.x * TY;      // base linear cell index
    const int b  = L >> 16;              // / (XX*YY)
    const int x  = (L >> 8) & 255;       // / YY % XX
    const int yb = L & 255;              // % YY (multiple of TY)

    const int tid = threadIdx.x;

    // Stage inverse indices; reset exclusive slice to 0 for the next launch.
    if (tid < TY) {
        int v = d_inv[L + tid];
        s_inv[tid] = v;
        d_inv[L + tid] = 0;
    }
    __syncthreads();

    // ---- load phase: 8 independent cp.async per thread ----
    const int f  = tid & 63;             // float4 group (channels 4f..4f+3)
    const int jb = tid >> 6;             // 0..3
    const int k  = f & 31;               // swizzle key

    #pragma unroll
    for (int wave = 0; wave < 8; wave++) {
        const int j = (wave << 2) + jb;  // y cell 0..31
        const int r = s_inv[j];
        const float* src = r ? feats + (size_t)(r - 1) * CC + (f << 2)
                             : feats;    // valid addr even when size==0
        const int size = r ? 16 : 0;     // 0 -> zero-fill 16 B
        const uint32_t dst =
            (uint32_t)__cvta_generic_to_shared(&tile4[f * TY + (j ^ k)]);
        asm volatile("cp.async.cg.shared.global [%0], [%1], 16, %2;"
                     :: "r"(dst), "l"(src), "r"(size));
    }
    asm volatile("cp.async.commit_group;");
    asm volatile("cp.async.wait_group 0;");
    __syncthreads();

    // ---- store phase: full 128 B output lines, streaming ----
    const int warp = tid >> 5;           // 0..7
    const int lane = tid & 31;           // = y within tile
    float* op = out + (size_t)b * CC * XY + (size_t)x * YY + yb + lane;
    #pragma unroll
    for (int i = 0; i < 8; i++) {
        const int ff = (warp << 3) + i;  // float4 group 0..63
        const float4 v = tile4[ff * TY + (lane ^ (ff & 31))];
        float* p = op + (size_t)(ff << 2) * XY;
        __stcs(p,          v.x);
        __stcs(p +     XY, v.y);
        __stcs(p + 2 * XY, v.z);
        __stcs(p + 3 * XY, v.w);
    }
}

// ---------------------------------------------------------------------------
// Launcher
// ---------------------------------------------------------------------------
extern "C" void kernel_launch(void* const* d_in, const int* in_sizes, int n_in,
                              void* d_out, int out_size) {
    const float* feats  = (const float*)d_in[0];
    const int*   coords = (const int*)d_in[1];
    float*       out    = (float*)d_out;

    const int n = in_sizes[1] / 3;  // number of sparse points

    build_inv_kernel<<<(n + 255) / 256, 256>>>(coords, n);
    gather_kernel<<<(BB * XX * YY) / TY, 256>>>(feats, out);
}